// round 10
// baseline (speedup 1.0000x reference)
#include <cuda_runtime.h>
#include <cstdint>

#define NN    50000
#define EE    800000
#define HH    128
#define GG    128
#define OUTD  10
#define NHOPS 4
#define NB    ((NN + 255) / 256)   // 196 scan blocks

// ---------------- device scratch (static, no runtime allocation) ----------------
__device__ __align__(16) float d_h0[NN * HH];
__device__ __align__(16) float d_h1[NN * HH];
__device__ __align__(16) float d_g[NN * HH];
__device__ float d_dinv[NN];
__device__ int   d_degcnt[NN];
__device__ int   d_rowptr[NN + 1];
__device__ int   d_cursor[NN];
__device__ int   d_esrc[EE];
__device__ float d_sums[GG * OUTD];
__device__ float d_cnt[GG];
__device__ int   d_stride;     // 1 = int32 inputs, 2 = int64 inputs
__device__ int   d_blksum[NB];
__device__ int   d_blkoff[NB];

__device__ __forceinline__ int clampi(int v, int lo, int hi) {
    return v < lo ? lo : (v > hi ? hi : v);
}

__device__ __forceinline__ uint32_t f2tf(float f) {
    uint32_t u;
    asm("cvt.rna.tf32.f32 %0, %1;" : "=r"(u) : "f"(f));
    return u;
}

// ---------------- dtype detection: int32 vs int64 edge_index -------------------
__global__ void detect_kernel(const int* __restrict__ ei_words) {
    __shared__ int nonzero;
    if (threadIdx.x == 0) nonzero = 0;
    __syncthreads();
    int w = ei_words[2 * threadIdx.x + 1];
    if (w != 0) atomicOr(&nonzero, 1);
    __syncthreads();
    if (threadIdx.x == 0) d_stride = nonzero ? 1 : 2;
}

// ---------------- zero per-launch state ----------------
__global__ void zero_kernel() {
    int i = blockIdx.x * blockDim.x + threadIdx.x;
    if (i < NN) { d_degcnt[i] = 0; d_cursor[i] = 0; }
    if (i < GG * OUTD) d_sums[i] = 0.0f;
    if (i < GG) d_cnt[i] = 0.0f;
}

// ---------------- in-degree count ----------------
__global__ void count_kernel(const int* __restrict__ ei) {
    int e = blockIdx.x * blockDim.x + threadIdx.x;
    if (e < EE) {
        int st = d_stride;
        int dst = clampi(ei[(size_t)st * (EE + e)], 0, NN - 1);
        atomicAdd(&d_degcnt[dst], 1);
    }
}

// ---------------- scan stages ----------------
__global__ __launch_bounds__(256) void scanA_kernel() {
    int i = blockIdx.x * 256 + threadIdx.x;
    int v = (i < NN) ? d_degcnt[i] : 0;
    int lane = threadIdx.x & 31, wid = threadIdx.x >> 5;
    int s = v;
    #pragma unroll
    for (int o = 16; o > 0; o >>= 1) s += __shfl_down_sync(0xffffffffu, s, o);
    __shared__ int ws[8];
    if (lane == 0) ws[wid] = s;
    __syncthreads();
    if (threadIdx.x == 0) {
        int t = 0;
        #pragma unroll
        for (int w = 0; w < 8; w++) t += ws[w];
        d_blksum[blockIdx.x] = t;
    }
}

__global__ __launch_bounds__(256) void scanB_kernel() {
    __shared__ int s_a[256], s_b[256];
    int t = threadIdx.x;
    int v = (t < NB) ? d_blksum[t] : 0;
    s_a[t] = v;
    __syncthreads();
    int* cur = s_a; int* nxt = s_b;
    for (int off = 1; off < 256; off <<= 1) {
        int x = cur[t];
        if (t >= off) x += cur[t - off];
        nxt[t] = x;
        __syncthreads();
        int* tmp = cur; cur = nxt; nxt = tmp;
    }
    if (t < NB) d_blkoff[t] = cur[t] - v;
    if (t == 0) d_rowptr[NN] = EE;
}

__global__ __launch_bounds__(256) void scanC_kernel() {
    int i = blockIdx.x * 256 + threadIdx.x;
    int v = (i < NN) ? d_degcnt[i] : 0;
    int lane = threadIdx.x & 31, wid = threadIdx.x >> 5;
    int incl = v;
    #pragma unroll
    for (int o = 1; o < 32; o <<= 1) {
        int y = __shfl_up_sync(0xffffffffu, incl, o);
        if (lane >= o) incl += y;
    }
    __shared__ int ws[8];
    if (lane == 31) ws[wid] = incl;
    __syncthreads();
    int woff = 0;
    #pragma unroll
    for (int w = 0; w < 8; w++) woff += (w < wid) ? ws[w] : 0;
    if (i < NN) {
        d_rowptr[i] = d_blkoff[blockIdx.x] + woff + incl - v;
        d_dinv[i] = rsqrtf(1.0f + (float)v);
    }
}

// ---------------- scatter edges into CSR buckets ----------------
__global__ void scatter_kernel(const int* __restrict__ ei) {
    int e = blockIdx.x * blockDim.x + threadIdx.x;
    if (e < EE) {
        int st = d_stride;
        int dst = clampi(ei[(size_t)st * (EE + e)], 0, NN - 1);
        int src = clampi(ei[(size_t)st * e],        0, NN - 1);
        int pos = d_rowptr[dst] + atomicAdd(&d_cursor[dst], 1);
        if (pos >= 0 && pos < EE) d_esrc[pos] = src;
    }
}

// ---------------- TF32 tensor-core GEMM v2 -------------------------------------
// Pre-converted tf32 operands in smem (no cvt in mainloop), XOR swizzle
// (conflict-free, no padding), double-buffered B chunks with reg prefetch.
// A: 64x128 tf32 bits, swizzle c4 ^= (r&7). B chunk: 16x128, swizzle c4 ^= (k&3)<<1.
__global__ __launch_bounds__(256) void gemm_tf32_kernel(
    const float* __restrict__ Aext, const float* __restrict__ B,
    const float* __restrict__ bias, int asel, int use_scale, int csel)
{
    __shared__ uint32_t Asu[64 * 128];      // 32 KB
    __shared__ uint32_t Bsu[2][16 * 128];   // 2 x 8 KB  (total 48 KB exactly)

    const float* A = (asel == 0) ? Aext : (asel == 1 ? d_h0 : d_h1);
    float* C = (csel == 0) ? d_g : (csel == 1 ? d_h0 : d_h1);

    int tid = threadIdx.x;
    int wid = tid >> 5, lane = tid & 31;
    int g = lane >> 2, t = lane & 3;
    int wm = wid & 1, wn = wid >> 1;        // warp grid 2 m x 4 n
    int row0 = blockIdx.x * 64;

    const float4* B4 = (const float4*)B;

    // load + convert A tile
    {
        const float4* A4 = (const float4*)A;
        uint4* As4 = (uint4*)Asu;
        #pragma unroll
        for (int i = 0; i < 8; i++) {
            int idx = i * 256 + tid;
            int r = idx >> 5, c4 = idx & 31;
            float4 v = (row0 + r < NN) ? A4[(size_t)(row0 + r) * 32 + c4]
                                       : make_float4(0.f, 0.f, 0.f, 0.f);
            uint4 u;
            u.x = f2tf(v.x); u.y = f2tf(v.y); u.z = f2tf(v.z); u.w = f2tf(v.w);
            As4[r * 32 + (c4 ^ (r & 7))] = u;
        }
    }
    // stage B chunk 0
    {
        uint4* Bd = (uint4*)Bsu[0];
        #pragma unroll
        for (int i = 0; i < 2; i++) {
            int idx = i * 256 + tid;
            int r = idx >> 5, c4 = idx & 31;
            float4 v = B4[(size_t)r * 32 + c4];
            uint4 u;
            u.x = f2tf(v.x); u.y = f2tf(v.y); u.z = f2tf(v.z); u.w = f2tf(v.w);
            Bd[r * 32 + (c4 ^ ((r & 3) << 1))] = u;
        }
    }
    __syncthreads();

    float acc[2][4][4];
    #pragma unroll
    for (int am = 0; am < 2; am++)
        #pragma unroll
        for (int an = 0; an < 4; an++)
            #pragma unroll
            for (int q = 0; q < 4; q++) acc[am][an][q] = 0.0f;

    for (int kc = 0; kc < 8; kc++) {
        // prefetch next B chunk into registers (overlaps with compute)
        float4 pf0, pf1;
        if (kc < 7) {
            int idx0 = tid,        r0 = idx0 >> 5, c40 = idx0 & 31;
            int idx1 = 256 + tid,  r1 = idx1 >> 5, c41 = idx1 & 31;
            pf0 = B4[(size_t)((kc + 1) * 16 + r0) * 32 + c40];
            pf1 = B4[(size_t)((kc + 1) * 16 + r1) * 32 + c41];
        }

        const uint32_t* Bc = Bsu[kc & 1];
        #pragma unroll
        for (int ka = 0; ka < 2; ka++) {
            int kq = (kc * 16 + ka * 8) >> 2;   // A col4 base
            int kb = ka * 8;

            uint32_t a[2][4];
            #pragma unroll
            for (int am = 0; am < 2; am++) {
                int r = wm * 32 + am * 16 + g;
                const uint32_t* Ap = Asu + r * 128;
                int q0 = ((kq)     ^ g) * 4 + t;
                int q1 = ((kq + 1) ^ g) * 4 + t;
                a[am][0] = Ap[q0];
                a[am][1] = Ap[8 * 128 + q0];
                a[am][2] = Ap[q1];
                a[am][3] = Ap[8 * 128 + q1];
            }
            uint32_t b[4][2];
            #pragma unroll
            for (int an = 0; an < 4; an++) {
                int bc = wn * 32 + an * 8 + g;
                int off = ((bc >> 2) ^ (t << 1)) * 4 + (bc & 3);
                b[an][0] = Bc[(kb + t) * 128 + off];
                b[an][1] = Bc[(kb + t + 4) * 128 + off];
            }
            #pragma unroll
            for (int am = 0; am < 2; am++)
                #pragma unroll
                for (int an = 0; an < 4; an++) {
                    asm volatile(
                        "mma.sync.aligned.m16n8k8.row.col.f32.tf32.tf32.f32 "
                        "{%0,%1,%2,%3}, {%4,%5,%6,%7}, {%8,%9}, {%0,%1,%2,%3};"
                        : "+f"(acc[am][an][0]), "+f"(acc[am][an][1]),
                          "+f"(acc[am][an][2]), "+f"(acc[am][an][3])
                        : "r"(a[am][0]), "r"(a[am][1]), "r"(a[am][2]), "r"(a[am][3]),
                          "r"(b[an][0]), "r"(b[an][1]));
                }
        }
        __syncthreads();
        if (kc < 7) {
            uint4* Bd = (uint4*)Bsu[(kc + 1) & 1];
            {
                int idx = tid, r = idx >> 5, c4 = idx & 31;
                uint4 u;
                u.x = f2tf(pf0.x); u.y = f2tf(pf0.y); u.z = f2tf(pf0.z); u.w = f2tf(pf0.w);
                Bd[r * 32 + (c4 ^ ((r & 3) << 1))] = u;
            }
            {
                int idx = 256 + tid, r = idx >> 5, c4 = idx & 31;
                uint4 u;
                u.x = f2tf(pf1.x); u.y = f2tf(pf1.y); u.z = f2tf(pf1.z); u.w = f2tf(pf1.w);
                Bd[r * 32 + (c4 ^ ((r & 3) << 1))] = u;
            }
            __syncthreads();
        }
    }

    // epilogue: c0:(g,2t) c1:(g,2t+1) c2:(g+8,2t) c3:(g+8,2t+1)
    #pragma unroll
    for (int am = 0; am < 2; am++) {
        int r0a = row0 + wm * 32 + am * 16;
        int rA = r0a + g;
        int rB = r0a + g + 8;
        float sA = 1.0f, sB = 1.0f;
        if (use_scale) {
            if (rA < NN) sA = d_dinv[rA];
            if (rB < NN) sB = d_dinv[rB];
        }
        #pragma unroll
        for (int an = 0; an < 4; an++) {
            int col = wn * 32 + an * 8 + 2 * t;
            float bx = bias ? bias[col]     : 0.0f;
            float by = bias ? bias[col + 1] : 0.0f;
            if (rA < NN) {
                float2 o;
                o.x = (acc[am][an][0] + bx) * sA;
                o.y = (acc[am][an][1] + by) * sA;
                *(float2*)(C + (size_t)rA * HH + col) = o;
            }
            if (rB < NN) {
                float2 o;
                o.x = (acc[am][an][2] + bx) * sB;
                o.y = (acc[am][an][3] + by) * sB;
                *(float2*)(C + (size_t)rB * HH + col) = o;
            }
        }
    }
}

// ---------------- neighborhood aggregation (warp per node, MLP=4) --------------
__global__ __launch_bounds__(256) void aggregate_kernel(
    const float* __restrict__ bias, int relu, int outsel)
{
    int node = blockIdx.x * 8 + (threadIdx.x >> 5);
    if (node >= NN) return;
    int lane = threadIdx.x & 31;
    float* out = (outsel == 1) ? d_h0 : d_h1;

    const float4* g4 = (const float4*)d_g;
    float4 acc = g4[(size_t)node * 32 + lane];   // self term

    int s = d_rowptr[node], e = d_rowptr[node + 1];
    int j = s;
    for (; j + 3 < e; j += 4) {
        int s0 = d_esrc[j], s1 = d_esrc[j + 1], s2 = d_esrc[j + 2], s3 = d_esrc[j + 3];
        float4 v0 = g4[(size_t)s0 * 32 + lane];
        float4 v1 = g4[(size_t)s1 * 32 + lane];
        float4 v2 = g4[(size_t)s2 * 32 + lane];
        float4 v3 = g4[(size_t)s3 * 32 + lane];
        acc.x += v0.x + v1.x + v2.x + v3.x;
        acc.y += v0.y + v1.y + v2.y + v3.y;
        acc.z += v0.z + v1.z + v2.z + v3.z;
        acc.w += v0.w + v1.w + v2.w + v3.w;
    }
    for (; j < e; j++) {
        int ss = d_esrc[j];
        float4 v = g4[(size_t)ss * 32 + lane];
        acc.x += v.x; acc.y += v.y; acc.z += v.z; acc.w += v.w;
    }

    float di = d_dinv[node];
    float4 b4 = ((const float4*)bias)[lane];
    float4 o;
    o.x = fmaf(acc.x, di, b4.x);
    o.y = fmaf(acc.y, di, b4.y);
    o.z = fmaf(acc.z, di, b4.z);
    o.w = fmaf(acc.w, di, b4.w);
    if (relu) {
        o.x = fmaxf(o.x, 0.f); o.y = fmaxf(o.y, 0.f);
        o.z = fmaxf(o.z, 0.f); o.w = fmaxf(o.w, 0.f);
    }
    ((float4*)out)[(size_t)node * 32 + lane] = o;
}

// ---------------- fused last-hop aggregation + classifier + pool ----------------
__global__ __launch_bounds__(256) void aggregate_cls_kernel(
    const float* __restrict__ bias, const int* __restrict__ batch,
    const float* __restrict__ Wc, const float* __restrict__ bc)
{
    __shared__ float sW[HH * OUTD];
    __shared__ float sB[OUTD];
    int tid = threadIdx.x;
    for (int i = tid; i < HH * OUTD; i += 256) sW[i] = Wc[i];
    if (tid < OUTD) sB[tid] = bc[tid];
    __syncthreads();

    int node = blockIdx.x * 8 + (tid >> 5);
    if (node >= NN) return;
    int lane = tid & 31;

    const float4* g4 = (const float4*)d_g;
    float4 acc = g4[(size_t)node * 32 + lane];

    int s = d_rowptr[node], e = d_rowptr[node + 1];
    int j = s;
    for (; j + 3 < e; j += 4) {
        int s0 = d_esrc[j], s1 = d_esrc[j + 1], s2 = d_esrc[j + 2], s3 = d_esrc[j + 3];
        float4 v0 = g4[(size_t)s0 * 32 + lane];
        float4 v1 = g4[(size_t)s1 * 32 + lane];
        float4 v2 = g4[(size_t)s2 * 32 + lane];
        float4 v3 = g4[(size_t)s3 * 32 + lane];
        acc.x += v0.x + v1.x + v2.x + v3.x;
        acc.y += v0.y + v1.y + v2.y + v3.y;
        acc.z += v0.z + v1.z + v2.z + v3.z;
        acc.w += v0.w + v1.w + v2.w + v3.w;
    }
    for (; j < e; j++) {
        int ss = d_esrc[j];
        float4 v = g4[(size_t)ss * 32 + lane];
        acc.x += v.x; acc.y += v.y; acc.z += v.z; acc.w += v.w;
    }

    float di = d_dinv[node];
    float4 b4 = ((const float4*)bias)[lane];
    float4 o;
    o.x = fmaf(acc.x, di, b4.x);
    o.y = fmaf(acc.y, di, b4.y);
    o.z = fmaf(acc.z, di, b4.z);
    o.w = fmaf(acc.w, di, b4.w);

    int c0 = 4 * lane;
    float p[OUTD];
    #pragma unroll
    for (int d = 0; d < OUTD; d++) {
        float v = o.x * sW[(c0 + 0) * OUTD + d];
        v = fmaf(o.y, sW[(c0 + 1) * OUTD + d], v);
        v = fmaf(o.z, sW[(c0 + 2) * OUTD + d], v);
        v = fmaf(o.w, sW[(c0 + 3) * OUTD + d], v);
        p[d] = v;
    }
    #pragma unroll
    for (int off = 16; off > 0; off >>= 1) {
        #pragma unroll
        for (int d = 0; d < OUTD; d++)
            p[d] += __shfl_xor_sync(0xffffffffu, p[d], off);
    }
    int st = d_stride;
    int b = clampi(batch[(size_t)st * node], 0, GG - 1);
    if (lane < OUTD) {
        float v = p[0];
        #pragma unroll
        for (int d = 1; d < OUTD; d++) v = (lane == d) ? p[d] : v;
        atomicAdd(&d_sums[b * OUTD + lane], v + sB[lane]);
    }
    if (lane == OUTD) atomicAdd(&d_cnt[b], 1.0f);
}

// ---------------- final divide ----------------
__global__ void finalize_kernel(float* __restrict__ out) {
    int i = blockIdx.x * blockDim.x + threadIdx.x;
    if (i < GG * OUTD) {
        float c = d_cnt[i / OUTD];
        out[i] = d_sums[i] / fmaxf(c, 1.0f);
    }
}

// ---------------- launch ----------------
extern "C" void kernel_launch(void* const* d_in, const int* in_sizes, int n_in,
                              void* d_out, int out_size) {
    const float* x      = (const float*)d_in[0];
    const int*   ei     = (const int*)d_in[1];
    const int*   batch  = (const int*)d_in[2];
    const float* W_in   = (const float*)d_in[3];
    const float* b_in   = (const float*)d_in[4];
    const float* W_hops = (const float*)d_in[5];
    const float* b_hops = (const float*)d_in[6];
    const float* W_cls  = (const float*)d_in[7];
    const float* b_cls  = (const float*)d_in[8];
    float* out = (float*)d_out;

    const int GB = (NN + 63) / 64;

    detect_kernel<<<1, 128>>>(ei);
    zero_kernel<<<(NN + 255) / 256, 256>>>();
    count_kernel<<<(EE + 255) / 256, 256>>>(ei);
    // encoder GEMM kept in slot 4 for stable ncu sampling
    gemm_tf32_kernel<<<GB, 256>>>(x, W_in, b_in, 0, 0, 1);
    scanA_kernel<<<NB, 256>>>();
    scanB_kernel<<<1, 256>>>();
    scanC_kernel<<<NB, 256>>>();
    scatter_kernel<<<(EE + 255) / 256, 256>>>(ei);

    int cur = 1;   // d_h0
    for (int hop = 0; hop < NHOPS; hop++) {
        int nxt = (cur == 1) ? 2 : 1;
        gemm_tf32_kernel<<<GB, 256>>>(nullptr, W_hops + (size_t)hop * HH * HH,
                                      nullptr, cur, 1, 0);
        if (hop < NHOPS - 1) {
            aggregate_kernel<<<(NN + 7) / 8, 256>>>(b_hops + hop * HH, 1, nxt);
        } else {
            aggregate_cls_kernel<<<(NN + 7) / 8, 256>>>(b_hops + hop * HH,
                                                        batch, W_cls, b_cls);
        }
        cur = nxt;
    }

    finalize_kernel<<<(GG * OUTD + 255) / 256, 256>>>(out);
}